// round 1
// baseline (speedup 1.0000x reference)
#include <cuda_runtime.h>

// Problem shapes (fixed for this dataset)
#define T_DIM   8192
#define IN_DIM  4096
#define OUT_DIM 4096
#define R_DIM   256
#define SCALE_F 4.0f

// Scratch for the effective weight W + SCALE * diag(b) B diag(d) A  (64 MB)
__device__ float g_weff[(size_t)OUT_DIM * IN_DIM];

// ---------------------------------------------------------------------------
// f32x2 packed-FMA helpers (Blackwell FFMA2 — only reachable via PTX)
// ---------------------------------------------------------------------------
__device__ __forceinline__ unsigned long long pack2(float lo, float hi) {
    unsigned long long r;
    asm("mov.b64 %0, {%1, %2};"
        : "=l"(r) : "r"(__float_as_uint(lo)), "r"(__float_as_uint(hi)));
    return r;
}

__device__ __forceinline__ void ffma2(unsigned long long& c,
                                      unsigned long long a,
                                      unsigned long long b) {
    asm("fma.rn.f32x2 %0, %1, %2, %0;" : "+l"(c) : "l"(a), "l"(b));
}

__device__ __forceinline__ float2 unpack2(unsigned long long v) {
    float2 f;
    unsigned int lo, hi;
    asm("mov.b64 {%0, %1}, %2;" : "=r"(lo), "=r"(hi) : "l"(v));
    f.x = __uint_as_float(lo);
    f.y = __uint_as_float(hi);
    return f;
}

// ---------------------------------------------------------------------------
// Kernel 1: Weff[o][i] = W[o][i] + SCALE * b[o] * sum_r B[o][r] * d[r] * A[r][i]
//   GEMM: M=OUT (o), N=IN (i), K=R=256
//   vB [OUT][R]  row-major  -> K contiguous (load like "x", transpose into smem)
//   vA [R][IN]   row-major  -> already [k][n], vectorized smem stores; d folded in
// ---------------------------------------------------------------------------
__global__ __launch_bounds__(256, 2) void vera_weff_kernel(
    const float* __restrict__ W,
    const float* __restrict__ vA,
    const float* __restrict__ vB,
    const float* __restrict__ vd,
    const float* __restrict__ vb)
{
    __shared__ float Asm[16][132];  // (d ⊙ A)[r][i_local]
    __shared__ float Bsm[16][132];  // vB^T    [r][o_local]

    const int tid   = threadIdx.x;
    const int tx    = tid & 15;
    const int ty    = tid >> 4;
    const int orow0 = blockIdx.y * 128;
    const int icol0 = blockIdx.x * 128;

    unsigned long long acc[8][4];
#pragma unroll
    for (int m = 0; m < 8; m++)
#pragma unroll
        for (int n = 0; n < 4; n++) acc[m][n] = 0ULL;

    for (int kt = 0; kt < R_DIM / 16; kt++) {
        // ---- load vB tile (128 o-rows x 16 r), transpose into Bsm[r][o]
        {
            const int lrow = tid >> 2;
            const int lk   = (tid & 3) << 2;
#pragma unroll
            for (int it = 0; it < 2; it++) {
                const int r = lrow + it * 64;
                float4 v = *(const float4*)&vB[(size_t)(orow0 + r) * R_DIM + kt * 16 + lk];
                Bsm[lk + 0][r] = v.x;
                Bsm[lk + 1][r] = v.y;
                Bsm[lk + 2][r] = v.z;
                Bsm[lk + 3][r] = v.w;
            }
        }
        // ---- load vA tile (16 r x 128 i), scale by d[r], vectorized store
        {
            const int krow = tid >> 5;          // 0..7
            const int ci   = (tid & 31) << 2;   // 0..124
#pragma unroll
            for (int it = 0; it < 2; it++) {
                const int r = krow + it * 8;
                const float dv = __ldg(&vd[kt * 16 + r]);
                float4 v = *(const float4*)&vA[(size_t)(kt * 16 + r) * IN_DIM + icol0 + ci];
                v.x *= dv; v.y *= dv; v.z *= dv; v.w *= dv;
                *(float4*)&Asm[r][ci] = v;
            }
        }
        __syncthreads();

        // ---- compute 8x8 microtile over 16 k-steps (f32x2 packed FMA)
#pragma unroll
        for (int k = 0; k < 16; k++) {
            float4 av0 = *(const float4*)&Bsm[k][ty * 8];
            float4 av1 = *(const float4*)&Bsm[k][ty * 8 + 4];
            unsigned long long a2[8];
            a2[0] = pack2(av0.x, av0.x); a2[1] = pack2(av0.y, av0.y);
            a2[2] = pack2(av0.z, av0.z); a2[3] = pack2(av0.w, av0.w);
            a2[4] = pack2(av1.x, av1.x); a2[5] = pack2(av1.y, av1.y);
            a2[6] = pack2(av1.z, av1.z); a2[7] = pack2(av1.w, av1.w);
            unsigned long long b2[4];
            b2[0] = *(const unsigned long long*)&Asm[k][tx * 8 + 0];
            b2[1] = *(const unsigned long long*)&Asm[k][tx * 8 + 2];
            b2[2] = *(const unsigned long long*)&Asm[k][tx * 8 + 4];
            b2[3] = *(const unsigned long long*)&Asm[k][tx * 8 + 6];
#pragma unroll
            for (int m = 0; m < 8; m++)
#pragma unroll
                for (int n = 0; n < 4; n++) ffma2(acc[m][n], a2[m], b2[n]);
        }
        __syncthreads();
    }

    // ---- epilogue: Weff = W + SCALE * b[o] * acc
    const float4 vbv0 = *(const float4*)&vb[orow0 + ty * 8];
    const float4 vbv1 = *(const float4*)&vb[orow0 + ty * 8 + 4];
    float vbm[8] = {vbv0.x, vbv0.y, vbv0.z, vbv0.w, vbv1.x, vbv1.y, vbv1.z, vbv1.w};

#pragma unroll
    for (int m = 0; m < 8; m++) {
        const int o = orow0 + ty * 8 + m;
        const float s = SCALE_F * vbm[m];
        const size_t off = (size_t)o * IN_DIM + icol0 + tx * 8;
        float4 w0 = *(const float4*)&W[off];
        float4 w1 = *(const float4*)&W[off + 4];
        float2 c0 = unpack2(acc[m][0]);
        float2 c1 = unpack2(acc[m][1]);
        float2 c2 = unpack2(acc[m][2]);
        float2 c3 = unpack2(acc[m][3]);
        float4 o0 = make_float4(w0.x + s * c0.x, w0.y + s * c0.y,
                                w0.z + s * c1.x, w0.w + s * c1.y);
        float4 o1 = make_float4(w1.x + s * c2.x, w1.y + s * c2.y,
                                w1.z + s * c3.x, w1.w + s * c3.y);
        *(float4*)&g_weff[off]     = o0;
        *(float4*)&g_weff[off + 4] = o1;
    }
}

// ---------------------------------------------------------------------------
// Kernel 2: y[t][o] = sum_i x[t][i] * Weff[o][i] + bias[o]
//   128x128x16 tiles, 256 threads, 8x8 microtile, f32x2 packed accumulators,
//   register-prefetch pipelined global loads.
// ---------------------------------------------------------------------------
__global__ __launch_bounds__(256, 2) void vera_main_gemm(
    const float* __restrict__ x,
    const float* __restrict__ bias,
    float* __restrict__ y)
{
    __shared__ float As[16][132];  // x    [k][t_local]
    __shared__ float Bs[16][132];  // Weff [k][o_local]

    const int tid  = threadIdx.x;
    const int tx   = tid & 15;
    const int ty   = tid >> 4;
    const int row0 = blockIdx.y * 128;  // t
    const int col0 = blockIdx.x * 128;  // o
    const int lrow = tid >> 2;          // 0..63
    const int lk   = (tid & 3) << 2;    // 0,4,8,12

    const float* xg = x      + (size_t)row0 * IN_DIM + lk;
    const float* wg = g_weff + (size_t)col0 * IN_DIM + lk;

    unsigned long long acc[8][4];
#pragma unroll
    for (int m = 0; m < 8; m++)
#pragma unroll
        for (int n = 0; n < 4; n++) acc[m][n] = 0ULL;

    float4 xa0, xa1, wa0, wa1;

#define LOAD_TILE(koff)                                                         \
    do {                                                                        \
        xa0 = *(const float4*)(xg + (size_t)(lrow)      * IN_DIM + (koff));     \
        xa1 = *(const float4*)(xg + (size_t)(lrow + 64) * IN_DIM + (koff));     \
        wa0 = *(const float4*)(wg + (size_t)(lrow)      * IN_DIM + (koff));     \
        wa1 = *(const float4*)(wg + (size_t)(lrow + 64) * IN_DIM + (koff));     \
    } while (0)

#define STORE_TILE()                                                            \
    do {                                                                        \
        As[lk + 0][lrow]      = xa0.x; As[lk + 1][lrow]      = xa0.y;           \
        As[lk + 2][lrow]      = xa0.z; As[lk + 3][lrow]      = xa0.w;           \
        As[lk + 0][lrow + 64] = xa1.x; As[lk + 1][lrow + 64] = xa1.y;           \
        As[lk + 2][lrow + 64] = xa1.z; As[lk + 3][lrow + 64] = xa1.w;           \
        Bs[lk + 0][lrow]      = wa0.x; Bs[lk + 1][lrow]      = wa0.y;           \
        Bs[lk + 2][lrow]      = wa0.z; Bs[lk + 3][lrow]      = wa0.w;           \
        Bs[lk + 0][lrow + 64] = wa1.x; Bs[lk + 1][lrow + 64] = wa1.y;           \
        Bs[lk + 2][lrow + 64] = wa1.z; Bs[lk + 3][lrow + 64] = wa1.w;           \
    } while (0)

#define COMPUTE_TILE()                                                          \
    do {                                                                        \
        _Pragma("unroll")                                                       \
        for (int k = 0; k < 16; k++) {                                          \
            float4 av0 = *(const float4*)&As[k][ty * 8];                        \
            float4 av1 = *(const float4*)&As[k][ty * 8 + 4];                    \
            unsigned long long a2[8];                                           \
            a2[0] = pack2(av0.x, av0.x); a2[1] = pack2(av0.y, av0.y);           \
            a2[2] = pack2(av0.z, av0.z); a2[3] = pack2(av0.w, av0.w);           \
            a2[4] = pack2(av1.x, av1.x); a2[5] = pack2(av1.y, av1.y);           \
            a2[6] = pack2(av1.z, av1.z); a2[7] = pack2(av1.w, av1.w);           \
            unsigned long long b2[4];                                           \
            b2[0] = *(const unsigned long long*)&Bs[k][tx * 8 + 0];             \
            b2[1] = *(const unsigned long long*)&Bs[k][tx * 8 + 2];             \
            b2[2] = *(const unsigned long long*)&Bs[k][tx * 8 + 4];             \
            b2[3] = *(const unsigned long long*)&Bs[k][tx * 8 + 6];             \
            _Pragma("unroll")                                                   \
            for (int m = 0; m < 8; m++)                                         \
                _Pragma("unroll")                                               \
                for (int n = 0; n < 4; n++) ffma2(acc[m][n], a2[m], b2[n]);     \
        }                                                                       \
    } while (0)

    // prologue
    LOAD_TILE(0);
    STORE_TILE();
    __syncthreads();

    for (int kt = 1; kt < IN_DIM / 16; kt++) {
        LOAD_TILE(kt * 16);   // prefetch next tile into registers
        COMPUTE_TILE();       // compute on current smem tile
        __syncthreads();
        STORE_TILE();
        __syncthreads();
    }
    COMPUTE_TILE();

    // ---- epilogue: + bias, write y
    const float4 bv0 = *(const float4*)&bias[col0 + tx * 8];
    const float4 bv1 = *(const float4*)&bias[col0 + tx * 8 + 4];

#pragma unroll
    for (int m = 0; m < 8; m++) {
        float2 c0 = unpack2(acc[m][0]);
        float2 c1 = unpack2(acc[m][1]);
        float2 c2 = unpack2(acc[m][2]);
        float2 c3 = unpack2(acc[m][3]);
        float4 o0 = make_float4(c0.x + bv0.x, c0.y + bv0.y,
                                c1.x + bv0.z, c1.y + bv0.w);
        float4 o1 = make_float4(c2.x + bv1.x, c2.y + bv1.y,
                                c3.x + bv1.z, c3.y + bv1.w);
        const size_t off = (size_t)(row0 + ty * 8 + m) * OUT_DIM + col0 + tx * 8;
        *(float4*)&y[off]     = o0;
        *(float4*)&y[off + 4] = o1;
    }

#undef LOAD_TILE
#undef STORE_TILE
#undef COMPUTE_TILE
}

// ---------------------------------------------------------------------------
// Launch
// Inputs (metadata order): x, base_weight, base_bias, vera_random_A,
//                          vera_random_B, vera_d, vera_b
// ---------------------------------------------------------------------------
extern "C" void kernel_launch(void* const* d_in, const int* in_sizes, int n_in,
                              void* d_out, int out_size)
{
    const float* x    = (const float*)d_in[0];
    const float* W    = (const float*)d_in[1];
    const float* bias = (const float*)d_in[2];
    const float* vA   = (const float*)d_in[3];
    const float* vB   = (const float*)d_in[4];
    const float* vd   = (const float*)d_in[5];
    const float* vb   = (const float*)d_in[6];
    float* y = (float*)d_out;

    dim3 gw(IN_DIM / 128, OUT_DIM / 128);   // 32 x 32
    vera_weff_kernel<<<gw, 256>>>(W, vA, vB, vd, vb);

    dim3 gy(OUT_DIM / 128, T_DIM / 128);    // 32 x 64
    vera_main_gemm<<<gy, 256>>>(x, bias, y);
}

// round 3
// speedup vs baseline: 7.6376x; 7.6376x over previous
#include <cuda_runtime.h>
#include <cuda_fp16.h>
#include <cstdint>

#define T_DIM   8192
#define IN_DIM  4096
#define OUT_DIM 4096
#define R_DIM   256
#define SCALE_F 4.0f

// Tiled + SW128-pre-swizzled fp16 operand buffers (16KB tiles: 128 rows x 64 K)
// g_xhi : [mblk 64][kblk 64][16KB]   (rows = t, cols = i)
// g_whi : [nblk 32][kblk 64][16KB]   (rows = o, cols = i)
__device__ __align__(128) __half g_xhi[(size_t)T_DIM  * IN_DIM];
__device__ __align__(128) __half g_whi[(size_t)OUT_DIM * IN_DIM];

// ---------------------------------------------------------------------------
// helpers
// ---------------------------------------------------------------------------
static __device__ __forceinline__ uint32_t sw128(uint32_t b) {
    return b ^ ((b >> 3) & 0x70);
}
static __device__ __forceinline__ uint32_t smem_u32(const void* p) {
    uint32_t a;
    asm("{ .reg .u64 t; cvta.to.shared.u64 t, %1; cvt.u32.u64 %0, t; }"
        : "=r"(a) : "l"(p));
    return a;
}
static __device__ __forceinline__ uint32_t h2u(__half a, __half b) {
    __half2 h = __halves2half2(a, b);
    return *(uint32_t*)&h;
}

#define MBARRIER_INIT(m, c) \
    asm volatile("mbarrier.init.shared.b64 [%0], %1;" :: "r"(m), "r"((uint32_t)(c)) : "memory")
#define MBARRIER_EXPECT_TX(m, b) \
    asm volatile("mbarrier.arrive.expect_tx.shared.b64 _, [%0], %1;" :: "r"(m), "r"((uint32_t)(b)) : "memory")
#define MBARRIER_ARRIVE(m) \
    asm volatile("mbarrier.arrive.shared.b64 _, [%0];" :: "r"(m) : "memory")

#define WAIT_PARITY(m, p) do {                                                    \
    uint32_t _m = (m), _p = (uint32_t)(p), _d;                                    \
    asm volatile("{\n\t.reg .pred P;\n\t"                                         \
        "mbarrier.try_wait.parity.acquire.cta.shared::cta.b64 P, [%1], %2;\n\t"   \
        "selp.b32 %0, 1, 0, P;\n\t}" : "=r"(_d) : "r"(_m), "r"(_p) : "memory");   \
    while (!_d) {                                                                 \
        asm volatile("{\n\t.reg .pred P;\n\t"                                     \
            "mbarrier.try_wait.parity.acquire.cta.shared::cta.b64 P, [%1], %2, 0x989680;\n\t" \
            "selp.b32 %0, 1, 0, P;\n\t}" : "=r"(_d) : "r"(_m), "r"(_p) : "memory"); \
    } } while (0)

static __device__ __forceinline__ void bulk_g2s(uint32_t dst, const void* src,
                                                uint32_t bytes, uint32_t mbar) {
    unsigned long long g = (unsigned long long)__cvta_generic_to_global(src);
    asm volatile("cp.async.bulk.shared::cta.global.mbarrier::complete_tx::bytes [%0], [%1], %2, [%3];"
                 :: "r"(dst), "l"(g), "r"(bytes), "r"(mbar) : "memory");
}

#define LDSM_X4(r, addr) \
    asm volatile("ldmatrix.sync.aligned.m8n8.x4.shared.b16 {%0,%1,%2,%3}, [%4];" \
                 : "=r"((r)[0]), "=r"((r)[1]), "=r"((r)[2]), "=r"((r)[3]) : "r"(addr))

#define MMA16816(c, a, b0, b1) \
    asm volatile("mma.sync.aligned.m16n8k16.row.col.f32.f16.f16.f32 " \
                 "{%0,%1,%2,%3}, {%4,%5,%6,%7}, {%8,%9}, {%0,%1,%2,%3};" \
                 : "+f"((c)[0]), "+f"((c)[1]), "+f"((c)[2]), "+f"((c)[3]) \
                 : "r"((a)[0]), "r"((a)[1]), "r"((a)[2]), "r"((a)[3]), \
                   "r"(b0), "r"(b1))

// ---------------------------------------------------------------------------
// f32x2 packed FMA helpers (Weff kernel)
// ---------------------------------------------------------------------------
__device__ __forceinline__ unsigned long long pack2(float lo, float hi) {
    unsigned long long r;
    asm("mov.b64 %0, {%1, %2};"
        : "=l"(r) : "r"(__float_as_uint(lo)), "r"(__float_as_uint(hi)));
    return r;
}
__device__ __forceinline__ void ffma2(unsigned long long& c, unsigned long long a,
                                      unsigned long long b) {
    asm("fma.rn.f32x2 %0, %1, %2, %0;" : "+l"(c) : "l"(a), "l"(b));
}
__device__ __forceinline__ float2 unpack2(unsigned long long v) {
    float2 f; unsigned int lo, hi;
    asm("mov.b64 {%0, %1}, %2;" : "=r"(lo), "=r"(hi) : "l"(v));
    f.x = __uint_as_float(lo); f.y = __uint_as_float(hi);
    return f;
}

// ---------------------------------------------------------------------------
// Kernel 1: Weff = W + SCALE * b[o] * (B d) (A) -> fp16, tiled + swizzled
// ---------------------------------------------------------------------------
__global__ __launch_bounds__(256, 2) void vera_weff_split(
    const float* __restrict__ W,
    const float* __restrict__ vA,
    const float* __restrict__ vB,
    const float* __restrict__ vd,
    const float* __restrict__ vb)
{
    __shared__ float Asm[16][132];
    __shared__ float Bsm[16][132];

    const int tid   = threadIdx.x;
    const int tx    = tid & 15;
    const int ty    = tid >> 4;
    const int orow0 = blockIdx.y * 128;
    const int icol0 = blockIdx.x * 128;

    unsigned long long acc[8][4];
#pragma unroll
    for (int m = 0; m < 8; m++)
#pragma unroll
        for (int n = 0; n < 4; n++) acc[m][n] = 0ULL;

    for (int kt = 0; kt < R_DIM / 16; kt++) {
        {
            const int lrow = tid >> 2;
            const int lk   = (tid & 3) << 2;
#pragma unroll
            for (int it = 0; it < 2; it++) {
                const int r = lrow + it * 64;
                float4 v = *(const float4*)&vB[(size_t)(orow0 + r) * R_DIM + kt * 16 + lk];
                Bsm[lk + 0][r] = v.x; Bsm[lk + 1][r] = v.y;
                Bsm[lk + 2][r] = v.z; Bsm[lk + 3][r] = v.w;
            }
        }
        {
            const int krow = tid >> 5;
            const int ci   = (tid & 31) << 2;
#pragma unroll
            for (int it = 0; it < 2; it++) {
                const int r = krow + it * 8;
                const float dv = __ldg(&vd[kt * 16 + r]);
                float4 v = *(const float4*)&vA[(size_t)(kt * 16 + r) * IN_DIM + icol0 + ci];
                v.x *= dv; v.y *= dv; v.z *= dv; v.w *= dv;
                *(float4*)&Asm[r][ci] = v;
            }
        }
        __syncthreads();
#pragma unroll
        for (int k = 0; k < 16; k++) {
            float4 av0 = *(const float4*)&Bsm[k][ty * 8];
            float4 av1 = *(const float4*)&Bsm[k][ty * 8 + 4];
            unsigned long long a2[8];
            a2[0] = pack2(av0.x, av0.x); a2[1] = pack2(av0.y, av0.y);
            a2[2] = pack2(av0.z, av0.z); a2[3] = pack2(av0.w, av0.w);
            a2[4] = pack2(av1.x, av1.x); a2[5] = pack2(av1.y, av1.y);
            a2[6] = pack2(av1.z, av1.z); a2[7] = pack2(av1.w, av1.w);
            unsigned long long b2[4];
            b2[0] = *(const unsigned long long*)&Asm[k][tx * 8 + 0];
            b2[1] = *(const unsigned long long*)&Asm[k][tx * 8 + 2];
            b2[2] = *(const unsigned long long*)&Asm[k][tx * 8 + 4];
            b2[3] = *(const unsigned long long*)&Asm[k][tx * 8 + 6];
#pragma unroll
            for (int m = 0; m < 8; m++)
#pragma unroll
                for (int n = 0; n < 4; n++) ffma2(acc[m][n], a2[m], b2[n]);
        }
        __syncthreads();
    }

    const float4 vbv0 = *(const float4*)&vb[orow0 + ty * 8];
    const float4 vbv1 = *(const float4*)&vb[orow0 + ty * 8 + 4];
    float vbm[8] = {vbv0.x, vbv0.y, vbv0.z, vbv0.w, vbv1.x, vbv1.y, vbv1.z, vbv1.w};

    const int kblk = blockIdx.x * 2 + (tx >> 3);
    const int cu   = (tx & 7) * 8;
    const size_t tb = ((size_t)blockIdx.y * 64 + kblk) * 16384;

#pragma unroll
    for (int m = 0; m < 8; m++) {
        const int row = ty * 8 + m;
        const int o   = orow0 + row;
        const float s = SCALE_F * vbm[m];
        const size_t off_w = (size_t)o * IN_DIM + icol0 + tx * 8;
        float4 w0 = *(const float4*)&W[off_w];
        float4 w1 = *(const float4*)&W[off_w + 4];
        float2 c0 = unpack2(acc[m][0]);
        float2 c1 = unpack2(acc[m][1]);
        float2 c2 = unpack2(acc[m][2]);
        float2 c3 = unpack2(acc[m][3]);
        float v[8] = {w0.x + s * c0.x, w0.y + s * c0.y, w0.z + s * c1.x, w0.w + s * c1.y,
                      w1.x + s * c2.x, w1.y + s * c2.y, w1.z + s * c3.x, w1.w + s * c3.y};
        __half h[8];
#pragma unroll
        for (int j = 0; j < 8; j++) h[j] = __float2half_rn(v[j]);
        uint4 hv = make_uint4(h2u(h[0], h[1]), h2u(h[2], h[3]), h2u(h[4], h[5]), h2u(h[6], h[7]));
        const uint32_t off = sw128((uint32_t)(row * 128 + cu * 2));
        *(uint4*)((char*)g_whi + tb + off) = hv;
    }
}

// ---------------------------------------------------------------------------
// Kernel 2: x -> fp16 (single rounding), tiled + swizzled
// ---------------------------------------------------------------------------
__global__ __launch_bounds__(256) void vera_x_split(const float* __restrict__ x)
{
    const uint32_t c    = blockIdx.x * 256 + threadIdx.x;   // chunk of 8 elems
    const uint32_t k8   = c & 511;
    const uint32_t t    = c >> 9;
    const uint32_t kblk = k8 >> 3;
    const uint32_t cu   = (k8 & 7) * 8;
    const uint32_t row  = t & 127;
    const uint32_t mblk = t >> 7;

    const float* src = x + (size_t)t * IN_DIM + kblk * 64 + cu;
    float4 a = *(const float4*)src;
    float4 b = *(const float4*)(src + 4);
    __half2 p0 = __floats2half2_rn(a.x, a.y);
    __half2 p1 = __floats2half2_rn(a.z, a.w);
    __half2 p2 = __floats2half2_rn(b.x, b.y);
    __half2 p3 = __floats2half2_rn(b.z, b.w);
    uint4 v = make_uint4(*(uint32_t*)&p0, *(uint32_t*)&p1, *(uint32_t*)&p2, *(uint32_t*)&p3);

    const uint32_t off = sw128(row * 128 + cu * 2);
    *(uint4*)((char*)g_xhi + ((size_t)mblk * 64 + kblk) * 16384 + off) = v;
}

// ---------------------------------------------------------------------------
// Kernel 3: mma.sync mainloop.
//   CTA tile: M=128 (t) x N=256 (o), K-chunk 64.
//   8 warps (2 M x 4 N), warp tile 64 x 64.
//   4-stage cp.async.bulk pipeline: stage = 16KB x-tile + 2 x 16KB w-tiles.
// ---------------------------------------------------------------------------
#define STAGES    4
#define STAGE_B   49152
#define SMEM_MAIN (1024 + STAGES * STAGE_B)

__global__ __launch_bounds__(256, 1) void vera_mma_main(
    const float* __restrict__ bias, float* __restrict__ y)
{
    extern __shared__ char smem[];
    const uint32_t sb = smem_u32(smem);
    const int tid  = threadIdx.x;
    const int lane = tid & 31;
    const int wid  = tid >> 5;
    const int warp_m = wid >> 2;   // 0..1
    const int warp_n = wid & 3;    // 0..3
    const int bN = blockIdx.x;     // 0..15 (o supertile of 256)
    const int bM = blockIdx.y;     // 0..63 (t tile of 128)

    const uint32_t FULL  = sb;        // 4 x 8B
    const uint32_t EMPTY = sb + 32;   // 4 x 8B
    const uint32_t STG0  = sb + 1024;

    if (tid == 0) {
        for (int s = 0; s < STAGES; s++) {
            MBARRIER_INIT(FULL  + 8 * s, 1);
            MBARRIER_INIT(EMPTY + 8 * s, 8);
        }
    }
    __syncthreads();

    const char* xsrc = (const char*)g_xhi + (size_t)bM * 64 * 16384;
    const char* wsrc = (const char*)g_whi + (size_t)(bN * 2) * 64 * 16384;

    // prologue fills
    if (tid == 0) {
#pragma unroll
        for (int s = 0; s < STAGES; s++) {
            const uint32_t base = STG0 + s * STAGE_B;
            MBARRIER_EXPECT_TX(FULL + 8 * s, STAGE_B);
            bulk_g2s(base,         xsrc + (size_t)s * 16384, 16384, FULL + 8 * s);
            bulk_g2s(base + 16384, wsrc + (size_t)s * 16384, 16384, FULL + 8 * s);
            bulk_g2s(base + 32768, wsrc + (size_t)(64 + s) * 16384, 16384, FULL + 8 * s);
        }
    }

    // lane-invariant address components (SW128 swizzled tiles, 128B rows)
    const int a_row      = warp_m * 64 + (lane & 15);
    const uint32_t a_rb  = (uint32_t)a_row * 128;
    const uint32_t amsk  = (uint32_t)(lane & 7) << 4;
    const uint32_t acol0 = (uint32_t)(lane >> 4) * 16;

    const int b_rowl     = (warp_n & 1) * 64 + (lane & 7) + ((lane >> 4) & 1) * 8;
    const uint32_t b_rb  = (uint32_t)((warp_n >> 1) * 16384 + b_rowl * 128);
    const uint32_t bmsk  = (uint32_t)(lane & 7) << 4;
    const uint32_t bcol0 = (uint32_t)((lane >> 3) & 1) * 16;

    float acc[4][8][4];
#pragma unroll
    for (int i = 0; i < 4; i++)
#pragma unroll
        for (int t = 0; t < 8; t++)
#pragma unroll
            for (int q = 0; q < 4; q++) acc[i][t][q] = 0.0f;

    for (int it = 0; it < 64; ++it) {
        const int s  = it & 3;
        const int ph = (it >> 2) & 1;
        WAIT_PARITY(FULL + 8 * s, ph);
        const uint32_t XA = STG0 + s * STAGE_B;
        const uint32_t WB = XA + 16384;

#pragma unroll
        for (int ks = 0; ks < 4; ks++) {
            const uint32_t acsw = (acol0 + ks * 32) ^ amsk;
            const uint32_t bcsw = (bcol0 + ks * 32) ^ bmsk;
            uint32_t A[4][4], B[4][4];
#pragma unroll
            for (int i = 0; i < 4; i++)
                LDSM_X4(A[i], XA + a_rb + i * 2048 + acsw);
#pragma unroll
            for (int j = 0; j < 4; j++)
                LDSM_X4(B[j], WB + b_rb + j * 2048 + bcsw);
#pragma unroll
            for (int i = 0; i < 4; i++)
#pragma unroll
                for (int j = 0; j < 4; j++) {
                    MMA16816(acc[i][2 * j],     A[i], B[j][0], B[j][1]);
                    MMA16816(acc[i][2 * j + 1], A[i], B[j][2], B[j][3]);
                }
        }

        __syncwarp();
        if (lane == 0) MBARRIER_ARRIVE(EMPTY + 8 * s);

        if (tid == 0 && it + STAGES < 64) {
            WAIT_PARITY(EMPTY + 8 * s, ph);   // wait consumption round it>>2
            const int nk = it + STAGES;
            const uint32_t base = STG0 + s * STAGE_B;
            MBARRIER_EXPECT_TX(FULL + 8 * s, STAGE_B);
            bulk_g2s(base,         xsrc + (size_t)nk * 16384, 16384, FULL + 8 * s);
            bulk_g2s(base + 16384, wsrc + (size_t)nk * 16384, 16384, FULL + 8 * s);
            bulk_g2s(base + 32768, wsrc + (size_t)(64 + nk) * 16384, 16384, FULL + 8 * s);
        }
    }

    // epilogue: y = acc + bias
    const int trow0 = bM * 128 + warp_m * 64 + (lane >> 2);
    const int col0g = bN * 256 + warp_n * 64 + (lane & 3) * 2;

#pragma unroll
    for (int t = 0; t < 8; t++) {
        const int col = col0g + t * 8;
        const float2 bv = *(const float2*)&bias[col];
#pragma unroll
        for (int i = 0; i < 4; i++) {
            const int r0 = trow0 + i * 16;
            float2 o0 = make_float2(acc[i][t][0] + bv.x, acc[i][t][1] + bv.y);
            float2 o1 = make_float2(acc[i][t][2] + bv.x, acc[i][t][3] + bv.y);
            *(float2*)&y[(size_t)r0 * OUT_DIM + col]       = o0;
            *(float2*)&y[(size_t)(r0 + 8) * OUT_DIM + col] = o1;
        }
    }
}

// ---------------------------------------------------------------------------
// Launch. Inputs: x, base_weight, base_bias, vera_random_A, vera_random_B,
//                 vera_d, vera_b
// ---------------------------------------------------------------------------
extern "C" void kernel_launch(void* const* d_in, const int* in_sizes, int n_in,
                              void* d_out, int out_size)
{
    const float* x    = (const float*)d_in[0];
    const float* W    = (const float*)d_in[1];
    const float* bias = (const float*)d_in[2];
    const float* vA   = (const float*)d_in[3];
    const float* vB   = (const float*)d_in[4];
    const float* vd   = (const float*)d_in[5];
    const float* vb   = (const float*)d_in[6];
    float* y = (float*)d_out;

    cudaFuncSetAttribute(vera_mma_main,
                         cudaFuncAttributeMaxDynamicSharedMemorySize, SMEM_MAIN);

    dim3 gw(IN_DIM / 128, OUT_DIM / 128);            // 32 x 32
    vera_weff_split<<<gw, 256>>>(W, vA, vB, vd, vb);

    vera_x_split<<<(T_DIM * IN_DIM / 8) / 256, 256>>>(x);

    dim3 gm(OUT_DIM / 256, T_DIM / 128);             // 16 x 64
    vera_mma_main<<<gm, 256, SMEM_MAIN>>>(bias, y);
}

// round 4
// speedup vs baseline: 9.0220x; 1.1813x over previous
#include <cuda_runtime.h>
#include <cuda_fp16.h>
#include <cstdint>

#define T_DIM   8192
#define IN_DIM  4096
#define OUT_DIM 4096
#define R_DIM   256
#define SCALE_F 4.0f

// Tiled + SW128-pre-swizzled fp16 operand buffers (16KB tiles: 128 rows x 64 K)
// g_xhi : [mblk 64][kblk 64][16KB]   (rows = t,  cols = i)
// g_whi : [nblk 32][kblk 64][16KB]   (rows = o,  cols = i)
// g_bh  : [oblk 32][rblk 4][16KB]    (rows = o,  cols = r)   (4*b/64 folded in)
// g_ahT : [iblk 32][rblk 4][16KB]    (rows = i,  cols = r)   (64*d folded in)
__device__ __align__(128) __half g_xhi[(size_t)T_DIM  * IN_DIM];
__device__ __align__(128) __half g_whi[(size_t)OUT_DIM * IN_DIM];
__device__ __align__(128) __half g_bh [(size_t)OUT_DIM * R_DIM];
__device__ __align__(128) __half g_ahT[(size_t)IN_DIM  * R_DIM];

// ---------------------------------------------------------------------------
// helpers
// ---------------------------------------------------------------------------
static __device__ __forceinline__ uint32_t sw128(uint32_t b) {
    return b ^ ((b >> 3) & 0x70);
}
static __device__ __forceinline__ uint32_t smem_u32(const void* p) {
    uint32_t a;
    asm("{ .reg .u64 t; cvta.to.shared.u64 t, %1; cvt.u32.u64 %0, t; }"
        : "=r"(a) : "l"(p));
    return a;
}
static __device__ __forceinline__ uint32_t h2u(__half a, __half b) {
    __half2 h = __halves2half2(a, b);
    return *(uint32_t*)&h;
}

#define MBARRIER_INIT(m, c) \
    asm volatile("mbarrier.init.shared.b64 [%0], %1;" :: "r"(m), "r"((uint32_t)(c)) : "memory")
#define MBARRIER_EXPECT_TX(m, b) \
    asm volatile("mbarrier.arrive.expect_tx.shared.b64 _, [%0], %1;" :: "r"(m), "r"((uint32_t)(b)) : "memory")
#define MBARRIER_ARRIVE(m) \
    asm volatile("mbarrier.arrive.shared.b64 _, [%0];" :: "r"(m) : "memory")

#define WAIT_PARITY(m, p) do {                                                    \
    uint32_t _m = (m), _p = (uint32_t)(p), _d;                                    \
    asm volatile("{\n\t.reg .pred P;\n\t"                                         \
        "mbarrier.try_wait.parity.acquire.cta.shared::cta.b64 P, [%1], %2;\n\t"   \
        "selp.b32 %0, 1, 0, P;\n\t}" : "=r"(_d) : "r"(_m), "r"(_p) : "memory");   \
    while (!_d) {                                                                 \
        asm volatile("{\n\t.reg .pred P;\n\t"                                     \
            "mbarrier.try_wait.parity.acquire.cta.shared::cta.b64 P, [%1], %2, 0x989680;\n\t" \
            "selp.b32 %0, 1, 0, P;\n\t}" : "=r"(_d) : "r"(_m), "r"(_p) : "memory"); \
    } } while (0)

static __device__ __forceinline__ void bulk_g2s(uint32_t dst, const void* src,
                                                uint32_t bytes, uint32_t mbar) {
    unsigned long long g = (unsigned long long)__cvta_generic_to_global(src);
    asm volatile("cp.async.bulk.shared::cta.global.mbarrier::complete_tx::bytes [%0], [%1], %2, [%3];"
                 :: "r"(dst), "l"(g), "r"(bytes), "r"(mbar) : "memory");
}

#define LDSM_X4(r, addr) \
    asm volatile("ldmatrix.sync.aligned.m8n8.x4.shared.b16 {%0,%1,%2,%3}, [%4];" \
                 : "=r"((r)[0]), "=r"((r)[1]), "=r"((r)[2]), "=r"((r)[3]) : "r"(addr))

#define MMA16816(c, a, b0, b1) \
    asm volatile("mma.sync.aligned.m16n8k16.row.col.f32.f16.f16.f32 " \
                 "{%0,%1,%2,%3}, {%4,%5,%6,%7}, {%8,%9}, {%0,%1,%2,%3};" \
                 : "+f"((c)[0]), "+f"((c)[1]), "+f"((c)[2]), "+f"((c)[3]) \
                 : "r"((a)[0]), "r"((a)[1]), "r"((a)[2]), "r"((a)[3]), \
                   "r"(b0), "r"(b1))

// ---------------------------------------------------------------------------
// Kernel 1a: Bh = fp16( (SCALE/64) * b[o] * vB[o][r] ), tiled + swizzled
// ---------------------------------------------------------------------------
__global__ __launch_bounds__(256) void vera_conv_bh(
    const float* __restrict__ vB, const float* __restrict__ vb)
{
    const uint32_t c   = blockIdx.x * 256 + threadIdx.x;  // chunk of 8 r-elems
    const uint32_t o   = c >> 5;
    const uint32_t r8  = c & 31;
    const uint32_t rblk = r8 >> 3;
    const uint32_t cu   = (r8 & 7) * 8;

    const float s = __ldg(&vb[o]) * (SCALE_F / 64.0f);
    const float* src = vB + (size_t)o * R_DIM + rblk * 64 + cu;
    float4 a = *(const float4*)src;
    float4 b = *(const float4*)(src + 4);
    __half h[8] = {__float2half_rn(a.x * s), __float2half_rn(a.y * s),
                   __float2half_rn(a.z * s), __float2half_rn(a.w * s),
                   __float2half_rn(b.x * s), __float2half_rn(b.y * s),
                   __float2half_rn(b.z * s), __float2half_rn(b.w * s)};
    uint4 v = make_uint4(h2u(h[0], h[1]), h2u(h[2], h[3]), h2u(h[4], h[5]), h2u(h[6], h[7]));
    const size_t tile = ((size_t)(o >> 7) * 4 + rblk) * 16384;
    const uint32_t off = sw128((o & 127) * 128 + cu * 2);
    *(uint4*)((char*)g_bh + tile + off) = v;
}

// ---------------------------------------------------------------------------
// Kernel 1b: AhT[i][r] = fp16( 64 * d[r] * vA[r][i] ), tiled + swizzled (transpose)
// ---------------------------------------------------------------------------
__global__ __launch_bounds__(256) void vera_conv_ahT(
    const float* __restrict__ vA, const float* __restrict__ vd)
{
    const uint32_t c  = blockIdx.x * 256 + threadIdx.x;   // (r, 4 i's)
    const uint32_t r  = c >> 10;
    const uint32_t i4 = (c & 1023) * 4;

    const float s = __ldg(&vd[r]) * 64.0f;
    float4 v = *(const float4*)&vA[(size_t)r * IN_DIM + i4];
    const float vv[4] = {v.x, v.y, v.z, v.w};
#pragma unroll
    for (int j = 0; j < 4; j++) {
        const uint32_t i = i4 + j;
        const size_t tile = ((size_t)(i >> 7) * 4 + (r >> 6)) * 16384;
        const uint32_t off = sw128((i & 127) * 128 + (r & 63) * 2);
        *(__half*)((char*)g_ahT + tile + off) = __float2half_rn(vv[j] * s);
    }
}

// ---------------------------------------------------------------------------
// Kernel 2: x -> fp16 (single rounding), tiled + swizzled
// ---------------------------------------------------------------------------
__global__ __launch_bounds__(256) void vera_x_split(const float* __restrict__ x)
{
    const uint32_t c    = blockIdx.x * 256 + threadIdx.x;   // chunk of 8 elems
    const uint32_t k8   = c & 511;
    const uint32_t t    = c >> 9;
    const uint32_t kblk = k8 >> 3;
    const uint32_t cu   = (k8 & 7) * 8;
    const uint32_t row  = t & 127;
    const uint32_t mblk = t >> 7;

    const float* src = x + (size_t)t * IN_DIM + kblk * 64 + cu;
    float4 a = *(const float4*)src;
    float4 b = *(const float4*)(src + 4);
    __half2 p0 = __floats2half2_rn(a.x, a.y);
    __half2 p1 = __floats2half2_rn(a.z, a.w);
    __half2 p2 = __floats2half2_rn(b.x, b.y);
    __half2 p3 = __floats2half2_rn(b.z, b.w);
    uint4 v = make_uint4(*(uint32_t*)&p0, *(uint32_t*)&p1, *(uint32_t*)&p2, *(uint32_t*)&p3);

    const uint32_t off = sw128(row * 128 + cu * 2);
    *(uint4*)((char*)g_xhi + ((size_t)mblk * 64 + kblk) * 16384 + off) = v;
}

// ---------------------------------------------------------------------------
// Kernel 3: Weff via HMMA.  delta = Bh @ AhT^T (K=256), Weff = W + delta -> fp16
//   CTA tile: M=128 (o) x N=256 (i); all 4 K-chunks prologue-loaded.
// ---------------------------------------------------------------------------
#define WSTAGE_B  49152
#define WSMEM     (1024 + 4 * WSTAGE_B)

__global__ __launch_bounds__(256, 1) void vera_weff_mma(const float* __restrict__ W)
{
    extern __shared__ char smem[];
    const uint32_t sb = smem_u32(smem);
    const int tid  = threadIdx.x;
    const int lane = tid & 31;
    const int wid  = tid >> 5;
    const int warp_m = wid >> 2;
    const int warp_n = wid & 3;
    const int bI = blockIdx.x;   // 0..15 (i supertile of 256)
    const int bO = blockIdx.y;   // 0..31 (o tile of 128)

    const uint32_t FULL = sb;
    const uint32_t STG0 = sb + 1024;

    if (tid == 0) {
        for (int s = 0; s < 4; s++) MBARRIER_INIT(FULL + 8 * s, 1);
    }
    __syncthreads();

    if (tid == 0) {
        const char* bhsrc = (const char*)g_bh  + (size_t)bO * 4 * 16384;
        const char* a0src = (const char*)g_ahT + (size_t)(bI * 2) * 4 * 16384;
        const char* a1src = (const char*)g_ahT + (size_t)(bI * 2 + 1) * 4 * 16384;
#pragma unroll
        for (int s = 0; s < 4; s++) {
            const uint32_t base = STG0 + s * WSTAGE_B;
            MBARRIER_EXPECT_TX(FULL + 8 * s, WSTAGE_B);
            bulk_g2s(base,         bhsrc + (size_t)s * 16384, 16384, FULL + 8 * s);
            bulk_g2s(base + 16384, a0src + (size_t)s * 16384, 16384, FULL + 8 * s);
            bulk_g2s(base + 32768, a1src + (size_t)s * 16384, 16384, FULL + 8 * s);
        }
    }

    // lane-invariant address components (SW128 swizzled tiles, 128B rows)
    const int a_row      = warp_m * 64 + (lane & 15);
    const uint32_t a_rb  = (uint32_t)a_row * 128;
    const uint32_t amsk  = (uint32_t)(lane & 7) << 4;
    const uint32_t acol0 = (uint32_t)(lane >> 4) * 16;

    const int b_rowl     = (warp_n & 1) * 64 + (lane & 7) + ((lane >> 4) & 1) * 8;
    const uint32_t b_rb  = (uint32_t)((warp_n >> 1) * 16384 + b_rowl * 128);
    const uint32_t bmsk  = (uint32_t)(lane & 7) << 4;
    const uint32_t bcol0 = (uint32_t)((lane >> 3) & 1) * 16;

    float acc[4][8][4];
#pragma unroll
    for (int i = 0; i < 4; i++)
#pragma unroll
        for (int t = 0; t < 8; t++)
#pragma unroll
            for (int q = 0; q < 4; q++) acc[i][t][q] = 0.0f;

#pragma unroll 1
    for (int it = 0; it < 4; ++it) {
        WAIT_PARITY(FULL + 8 * it, 0);
        const uint32_t XA = STG0 + it * WSTAGE_B;
        const uint32_t WB = XA + 16384;
#pragma unroll
        for (int ks = 0; ks < 4; ks++) {
            const uint32_t acsw = (acol0 + ks * 32) ^ amsk;
            const uint32_t bcsw = (bcol0 + ks * 32) ^ bmsk;
            uint32_t A[4][4], B[4][4];
#pragma unroll
            for (int i = 0; i < 4; i++)
                LDSM_X4(A[i], XA + a_rb + i * 2048 + acsw);
#pragma unroll
            for (int j = 0; j < 4; j++)
                LDSM_X4(B[j], WB + b_rb + j * 2048 + bcsw);
#pragma unroll
            for (int i = 0; i < 4; i++)
#pragma unroll
                for (int j = 0; j < 4; j++) {
                    MMA16816(acc[i][2 * j],     A[i], B[j][0], B[j][1]);
                    MMA16816(acc[i][2 * j + 1], A[i], B[j][2], B[j][3]);
                }
        }
    }

    // epilogue: Weff = W + delta -> fp16, write into g_whi tile layout
    const int trow0 = warp_m * 64 + (lane >> 2);         // o within 128
    const int col0  = warp_n * 64 + (lane & 3) * 2;      // i within 256

#pragma unroll
    for (int t = 0; t < 8; t++) {
        const int col = col0 + t * 8;                    // i local (0..255)
        const int ig  = bI * 256 + col;                  // i global
        const size_t tile = ((size_t)bO * 64 + (ig >> 6)) * 16384;
        const uint32_t cu2 = (uint32_t)(col & 63) * 2;
#pragma unroll
        for (int i = 0; i < 4; i++) {
            const int r0 = trow0 + i * 16;               // o within 128
            const float2 w0 = *(const float2*)&W[(size_t)(bO * 128 + r0) * IN_DIM + ig];
            const float2 w1 = *(const float2*)&W[(size_t)(bO * 128 + r0 + 8) * IN_DIM + ig];
            const uint32_t v0 = h2u(__float2half_rn(w0.x + acc[i][t][0]),
                                    __float2half_rn(w0.y + acc[i][t][1]));
            const uint32_t v1 = h2u(__float2half_rn(w1.x + acc[i][t][2]),
                                    __float2half_rn(w1.y + acc[i][t][3]));
            *(uint32_t*)((char*)g_whi + tile + sw128((uint32_t)r0 * 128 + cu2))       = v0;
            *(uint32_t*)((char*)g_whi + tile + sw128((uint32_t)(r0 + 8) * 128 + cu2)) = v1;
        }
    }
}

// ---------------------------------------------------------------------------
// Kernel 4: mma.sync mainloop (unchanged from R3).
//   CTA tile: M=128 (t) x N=256 (o), K-chunk 64, 8 warps, warp tile 64x64,
//   4-stage cp.async.bulk pipeline.
// ---------------------------------------------------------------------------
#define STAGES    4
#define STAGE_B   49152
#define SMEM_MAIN (1024 + STAGES * STAGE_B)

__global__ __launch_bounds__(256, 1) void vera_mma_main(
    const float* __restrict__ bias, float* __restrict__ y)
{
    extern __shared__ char smem[];
    const uint32_t sb = smem_u32(smem);
    const int tid  = threadIdx.x;
    const int lane = tid & 31;
    const int wid  = tid >> 5;
    const int warp_m = wid >> 2;
    const int warp_n = wid & 3;
    const int bN = blockIdx.x;
    const int bM = blockIdx.y;

    const uint32_t FULL  = sb;
    const uint32_t EMPTY = sb + 32;
    const uint32_t STG0  = sb + 1024;

    if (tid == 0) {
        for (int s = 0; s < STAGES; s++) {
            MBARRIER_INIT(FULL  + 8 * s, 1);
            MBARRIER_INIT(EMPTY + 8 * s, 8);
        }
    }
    __syncthreads();

    const char* xsrc = (const char*)g_xhi + (size_t)bM * 64 * 16384;
    const char* wsrc = (const char*)g_whi + (size_t)(bN * 2) * 64 * 16384;

    if (tid == 0) {
#pragma unroll
        for (int s = 0; s < STAGES; s++) {
            const uint32_t base = STG0 + s * STAGE_B;
            MBARRIER_EXPECT_TX(FULL + 8 * s, STAGE_B);
            bulk_g2s(base,         xsrc + (size_t)s * 16384, 16384, FULL + 8 * s);
            bulk_g2s(base + 16384, wsrc + (size_t)s * 16384, 16384, FULL + 8 * s);
            bulk_g2s(base + 32768, wsrc + (size_t)(64 + s) * 16384, 16384, FULL + 8 * s);
        }
    }

    const int a_row      = warp_m * 64 + (lane & 15);
    const uint32_t a_rb  = (uint32_t)a_row * 128;
    const uint32_t amsk  = (uint32_t)(lane & 7) << 4;
    const uint32_t acol0 = (uint32_t)(lane >> 4) * 16;

    const int b_rowl     = (warp_n & 1) * 64 + (lane & 7) + ((lane >> 4) & 1) * 8;
    const uint32_t b_rb  = (uint32_t)((warp_n >> 1) * 16384 + b_rowl * 128);
    const uint32_t bmsk  = (uint32_t)(lane & 7) << 4;
    const uint32_t bcol0 = (uint32_t)((lane >> 3) & 1) * 16;

    float acc[4][8][4];
#pragma unroll
    for (int i = 0; i < 4; i++)
#pragma unroll
        for (int t = 0; t < 8; t++)
#pragma unroll
            for (int q = 0; q < 4; q++) acc[i][t][q] = 0.0f;

    for (int it = 0; it < 64; ++it) {
        const int s  = it & 3;
        const int ph = (it >> 2) & 1;
        WAIT_PARITY(FULL + 8 * s, ph);
        const uint32_t XA = STG0 + s * STAGE_B;
        const uint32_t WB = XA + 16384;

#pragma unroll
        for (int ks = 0; ks < 4; ks++) {
            const uint32_t acsw = (acol0 + ks * 32) ^ amsk;
            const uint32_t bcsw = (bcol0 + ks * 32) ^ bmsk;
            uint32_t A[4][4], B[4][4];
#pragma unroll
            for (int i = 0; i < 4; i++)
                LDSM_X4(A[i], XA + a_rb + i * 2048 + acsw);
#pragma unroll
            for (int j = 0; j < 4; j++)
                LDSM_X4(B[j], WB + b_rb + j * 2048 + bcsw);
#pragma unroll
            for (int i = 0; i < 4; i++)
#pragma unroll
                for (int j = 0; j < 4; j++) {
                    MMA16816(acc[i][2 * j],     A[i], B[j][0], B[j][1]);
                    MMA16816(acc[i][2 * j + 1], A[i], B[j][2], B[j][3]);
                }
        }

        __syncwarp();
        if (lane == 0) MBARRIER_ARRIVE(EMPTY + 8 * s);

        if (tid == 0 && it + STAGES < 64) {
            WAIT_PARITY(EMPTY + 8 * s, ph);
            const int nk = it + STAGES;
            const uint32_t base = STG0 + s * STAGE_B;
            MBARRIER_EXPECT_TX(FULL + 8 * s, STAGE_B);
            bulk_g2s(base,         xsrc + (size_t)nk * 16384, 16384, FULL + 8 * s);
            bulk_g2s(base + 16384, wsrc + (size_t)nk * 16384, 16384, FULL + 8 * s);
            bulk_g2s(base + 32768, wsrc + (size_t)(64 + nk) * 16384, 16384, FULL + 8 * s);
        }
    }

    const int trow0 = bM * 128 + warp_m * 64 + (lane >> 2);
    const int col0g = bN * 256 + warp_n * 64 + (lane & 3) * 2;

#pragma unroll
    for (int t = 0; t < 8; t++) {
        const int col = col0g + t * 8;
        const float2 bv = *(const float2*)&bias[col];
#pragma unroll
        for (int i = 0; i < 4; i++) {
            const int r0 = trow0 + i * 16;
            float2 o0 = make_float2(acc[i][t][0] + bv.x, acc[i][t][1] + bv.y);
            float2 o1 = make_float2(acc[i][t][2] + bv.x, acc[i][t][3] + bv.y);
            *(float2*)&y[(size_t)r0 * OUT_DIM + col]       = o0;
            *(float2*)&y[(size_t)(r0 + 8) * OUT_DIM + col] = o1;
        }
    }
}

// ---------------------------------------------------------------------------
// Launch. Inputs: x, base_weight, base_bias, vera_random_A, vera_random_B,
//                 vera_d, vera_b
// ---------------------------------------------------------------------------
extern "C" void kernel_launch(void* const* d_in, const int* in_sizes, int n_in,
                              void* d_out, int out_size)
{
    const float* x    = (const float*)d_in[0];
    const float* W    = (const float*)d_in[1];
    const float* bias = (const float*)d_in[2];
    const float* vA   = (const float*)d_in[3];
    const float* vB   = (const float*)d_in[4];
    const float* vd   = (const float*)d_in[5];
    const float* vb   = (const float*)d_in[6];
    float* y = (float*)d_out;

    cudaFuncSetAttribute(vera_weff_mma,
                         cudaFuncAttributeMaxDynamicSharedMemorySize, WSMEM);
    cudaFuncSetAttribute(vera_mma_main,
                         cudaFuncAttributeMaxDynamicSharedMemorySize, SMEM_MAIN);

    // prep: fp16 operand conversions
    vera_conv_bh <<<(OUT_DIM * R_DIM / 8) / 256, 256>>>(vB, vb);
    vera_conv_ahT<<<(R_DIM * IN_DIM / 4) / 256, 256>>>(vA, vd);
    vera_x_split <<<(T_DIM * IN_DIM / 8) / 256, 256>>>(x);

    // Weff = W + delta via tensor cores
    dim3 gweff(IN_DIM / 256, OUT_DIM / 128);   // 16 x 32
    vera_weff_mma<<<gweff, 256, WSMEM>>>(W);

    // main GEMM
    dim3 gm(OUT_DIM / 256, T_DIM / 128);       // 16 x 64
    vera_mma_main<<<gm, 256, SMEM_MAIN>>>(bias, y);
}

// round 5
// speedup vs baseline: 9.4073x; 1.0427x over previous
#include <cuda_runtime.h>
#include <cuda_fp16.h>
#include <cstdint>

#define T_DIM   8192
#define IN_DIM  4096
#define OUT_DIM 4096
#define R_DIM   256
#define SCALE_F 4.0f
#define NSM     148
#define NTILES  1024   /* 16 (o/256) x 64 (t/128) */

// Tiled + SW128-pre-swizzled fp16 operand buffers (16KB tiles: 128 rows x 64 cols)
// g_xhi : [mblk 64][kblk 64][16KB]   (rows = t,  cols = i)
// g_whi : [oblk 32][kblk 64][16KB]   (rows = o,  cols = i)
// g_bh  : [oblk 32][rblk 4][16KB]    (rows = o,  cols = r)   (4*b/64 folded in)
// g_ahT : [iblk 32][rblk 4][16KB]    (rows = i,  cols = r)   (64*d folded in)
__device__ __align__(128) __half g_xhi[(size_t)T_DIM  * IN_DIM];
__device__ __align__(128) __half g_whi[(size_t)OUT_DIM * IN_DIM];
__device__ __align__(128) __half g_bh [(size_t)OUT_DIM * R_DIM];
__device__ __align__(128) __half g_ahT[(size_t)IN_DIM  * R_DIM];

// ---------------------------------------------------------------------------
// helpers
// ---------------------------------------------------------------------------
static __device__ __forceinline__ uint32_t sw128(uint32_t b) {
    return b ^ ((b >> 3) & 0x70);
}
static __device__ __forceinline__ uint32_t smem_u32(const void* p) {
    uint32_t a;
    asm("{ .reg .u64 t; cvta.to.shared.u64 t, %1; cvt.u32.u64 %0, t; }"
        : "=r"(a) : "l"(p));
    return a;
}
static __device__ __forceinline__ uint32_t h2u(__half a, __half b) {
    __half2 h = __halves2half2(a, b);
    return *(uint32_t*)&h;
}

#define MBARRIER_INIT(m, c) \
    asm volatile("mbarrier.init.shared.b64 [%0], %1;" :: "r"(m), "r"((uint32_t)(c)) : "memory")
#define MBARRIER_EXPECT_TX(m, b) \
    asm volatile("mbarrier.arrive.expect_tx.shared.b64 _, [%0], %1;" :: "r"(m), "r"((uint32_t)(b)) : "memory")
#define MBARRIER_ARRIVE(m) \
    asm volatile("mbarrier.arrive.shared.b64 _, [%0];" :: "r"(m) : "memory")

#define WAIT_PARITY(m, p) do {                                                    \
    uint32_t _m = (m), _p = (uint32_t)(p), _d;                                    \
    asm volatile("{\n\t.reg .pred P;\n\t"                                         \
        "mbarrier.try_wait.parity.acquire.cta.shared::cta.b64 P, [%1], %2;\n\t"   \
        "selp.b32 %0, 1, 0, P;\n\t}" : "=r"(_d) : "r"(_m), "r"(_p) : "memory");   \
    while (!_d) {                                                                 \
        asm volatile("{\n\t.reg .pred P;\n\t"                                     \
            "mbarrier.try_wait.parity.acquire.cta.shared::cta.b64 P, [%1], %2, 0x989680;\n\t" \
            "selp.b32 %0, 1, 0, P;\n\t}" : "=r"(_d) : "r"(_m), "r"(_p) : "memory"); \
    } } while (0)

static __device__ __forceinline__ void bulk_g2s(uint32_t dst, const void* src,
                                                uint32_t bytes, uint32_t mbar) {
    unsigned long long g = (unsigned long long)__cvta_generic_to_global(src);
    asm volatile("cp.async.bulk.shared::cta.global.mbarrier::complete_tx::bytes [%0], [%1], %2, [%3];"
                 :: "r"(dst), "l"(g), "r"(bytes), "r"(mbar) : "memory");
}

#define LDSM_X4(r, addr) \
    asm volatile("ldmatrix.sync.aligned.m8n8.x4.shared.b16 {%0,%1,%2,%3}, [%4];" \
                 : "=r"((r)[0]), "=r"((r)[1]), "=r"((r)[2]), "=r"((r)[3]) : "r"(addr))

#define MMA16816(c, a, b0, b1) \
    asm volatile("mma.sync.aligned.m16n8k16.row.col.f32.f16.f16.f32 " \
                 "{%0,%1,%2,%3}, {%4,%5,%6,%7}, {%8,%9}, {%0,%1,%2,%3};" \
                 : "+f"((c)[0]), "+f"((c)[1]), "+f"((c)[2]), "+f"((c)[3]) \
                 : "r"((a)[0]), "r"((a)[1]), "r"((a)[2]), "r"((a)[3]), \
                   "r"(b0), "r"(b1))

// ---------------------------------------------------------------------------
// Kernel 1: fused operand conversion (Bh and AhT)
// ---------------------------------------------------------------------------
__global__ __launch_bounds__(256) void vera_conv(
    const float* __restrict__ vB, const float* __restrict__ vb,
    const float* __restrict__ vA, const float* __restrict__ vd)
{
    if (blockIdx.x < 512) {
        // Bh = fp16( (SCALE/64) * b[o] * vB[o][r] )
        const uint32_t c    = blockIdx.x * 256 + threadIdx.x;
        const uint32_t o    = c >> 5;
        const uint32_t r8   = c & 31;
        const uint32_t rblk = r8 >> 3;
        const uint32_t cu   = (r8 & 7) * 8;

        const float s = __ldg(&vb[o]) * (SCALE_F / 64.0f);
        const float* src = vB + (size_t)o * R_DIM + rblk * 64 + cu;
        float4 a = *(const float4*)src;
        float4 b = *(const float4*)(src + 4);
        __half h[8] = {__float2half_rn(a.x * s), __float2half_rn(a.y * s),
                       __float2half_rn(a.z * s), __float2half_rn(a.w * s),
                       __float2half_rn(b.x * s), __float2half_rn(b.y * s),
                       __float2half_rn(b.z * s), __float2half_rn(b.w * s)};
        uint4 v = make_uint4(h2u(h[0], h[1]), h2u(h[2], h[3]),
                             h2u(h[4], h[5]), h2u(h[6], h[7]));
        const size_t tile = ((size_t)(o >> 7) * 4 + rblk) * 16384;
        const uint32_t off = sw128((o & 127) * 128 + cu * 2);
        *(uint4*)((char*)g_bh + tile + off) = v;
    } else {
        // AhT[i][r] = fp16( 64 * d[r] * vA[r][i] )  (transpose)
        const uint32_t c  = (blockIdx.x - 512) * 256 + threadIdx.x;
        const uint32_t r  = c >> 10;
        const uint32_t i4 = (c & 1023) * 4;

        const float s = __ldg(&vd[r]) * 64.0f;
        float4 v = *(const float4*)&vA[(size_t)r * IN_DIM + i4];
        const float vv[4] = {v.x, v.y, v.z, v.w};
#pragma unroll
        for (int j = 0; j < 4; j++) {
            const uint32_t i = i4 + j;
            const size_t tile = ((size_t)(i >> 7) * 4 + (r >> 6)) * 16384;
            const uint32_t off = sw128((i & 127) * 128 + (r & 63) * 2);
            *(__half*)((char*)g_ahT + tile + off) = __float2half_rn(vv[j] * s);
        }
    }
}

// ---------------------------------------------------------------------------
// Kernel 2: x -> fp16 (single rounding), tiled + swizzled
// ---------------------------------------------------------------------------
__global__ __launch_bounds__(256) void vera_x_split(const float* __restrict__ x)
{
    const uint32_t c    = blockIdx.x * 256 + threadIdx.x;
    const uint32_t k8   = c & 511;
    const uint32_t t    = c >> 9;
    const uint32_t kblk = k8 >> 3;
    const uint32_t cu   = (k8 & 7) * 8;
    const uint32_t row  = t & 127;
    const uint32_t mblk = t >> 7;

    const float* src = x + (size_t)t * IN_DIM + kblk * 64 + cu;
    float4 a = *(const float4*)src;
    float4 b = *(const float4*)(src + 4);
    __half2 p0 = __floats2half2_rn(a.x, a.y);
    __half2 p1 = __floats2half2_rn(a.z, a.w);
    __half2 p2 = __floats2half2_rn(b.x, b.y);
    __half2 p3 = __floats2half2_rn(b.z, b.w);
    uint4 v = make_uint4(*(uint32_t*)&p0, *(uint32_t*)&p1, *(uint32_t*)&p2, *(uint32_t*)&p3);

    const uint32_t off = sw128(row * 128 + cu * 2);
    *(uint4*)((char*)g_xhi + ((size_t)mblk * 64 + kblk) * 16384 + off) = v;
}

// ---------------------------------------------------------------------------
// Kernel 3: Weff via HMMA, v2: M=128(o) x N=128(i), K=256, 3-stage pipeline,
//           2 CTAs/SM. delta = Bh @ AhT^T, Weff = W + delta -> fp16 tiles.
// ---------------------------------------------------------------------------
#define WSTG_B  32768
#define WSMEM   (1024 + 3 * WSTG_B)

__global__ __launch_bounds__(256, 2) void vera_weff_mma(const float* __restrict__ W)
{
    extern __shared__ char smem[];
    const uint32_t sb = smem_u32(smem);
    const int tid  = threadIdx.x;
    const int lane = tid & 31;
    const int wid  = tid >> 5;
    const int warp_m = wid >> 2;   // 0..1 (o)
    const int warp_n = wid & 3;    // 0..3 (i, 32 each)
    const int bI = blockIdx.x;     // 0..31 (i tile of 128)
    const int bO = blockIdx.y;     // 0..31 (o tile of 128)

    const uint32_t FULL  = sb;
    const uint32_t EMPTY = sb + 32;
    const uint32_t STG0  = sb + 1024;

    if (tid == 0) {
        for (int s = 0; s < 3; s++) {
            MBARRIER_INIT(FULL  + 8 * s, 1);
            MBARRIER_INIT(EMPTY + 8 * s, 8);
        }
    }
    __syncthreads();

    const char* bhsrc = (const char*)g_bh  + (size_t)bO * 4 * 16384;
    const char* ahsrc = (const char*)g_ahT + (size_t)bI * 4 * 16384;

    if (tid == 0) {
#pragma unroll
        for (int s = 0; s < 3; s++) {
            const uint32_t base = STG0 + s * WSTG_B;
            MBARRIER_EXPECT_TX(FULL + 8 * s, WSTG_B);
            bulk_g2s(base,         bhsrc + (size_t)s * 16384, 16384, FULL + 8 * s);
            bulk_g2s(base + 16384, ahsrc + (size_t)s * 16384, 16384, FULL + 8 * s);
        }
    }

    const int a_row      = warp_m * 64 + (lane & 15);
    const uint32_t a_rb  = (uint32_t)a_row * 128;
    const uint32_t amsk  = (uint32_t)(lane & 7) << 4;
    const uint32_t acol0 = (uint32_t)(lane >> 4) * 16;

    const int b_rowl     = warp_n * 32 + (lane & 7) + ((lane >> 4) & 1) * 8;
    const uint32_t b_rb  = (uint32_t)b_rowl * 128;
    const uint32_t bmsk  = (uint32_t)(lane & 7) << 4;
    const uint32_t bcol0 = (uint32_t)((lane >> 3) & 1) * 16;

    float acc[4][4][4];
#pragma unroll
    for (int i = 0; i < 4; i++)
#pragma unroll
        for (int t = 0; t < 4; t++)
#pragma unroll
            for (int q = 0; q < 4; q++) acc[i][t][q] = 0.0f;

#pragma unroll 1
    for (int it = 0; it < 4; ++it) {
        const int s  = it % 3;
        const int ph = (it / 3) & 1;
        WAIT_PARITY(FULL + 8 * s, ph);
        const uint32_t XA = STG0 + s * WSTG_B;
        const uint32_t WB = XA + 16384;
#pragma unroll
        for (int ks = 0; ks < 4; ks++) {
            const uint32_t acsw = (acol0 + ks * 32) ^ amsk;
            const uint32_t bcsw = (bcol0 + ks * 32) ^ bmsk;
            uint32_t A[4][4], B[2][4];
#pragma unroll
            for (int i = 0; i < 4; i++)
                LDSM_X4(A[i], XA + a_rb + i * 2048 + acsw);
#pragma unroll
            for (int j = 0; j < 2; j++)
                LDSM_X4(B[j], WB + b_rb + j * 2048 + bcsw);
#pragma unroll
            for (int i = 0; i < 4; i++)
#pragma unroll
                for (int j = 0; j < 2; j++) {
                    MMA16816(acc[i][2 * j],     A[i], B[j][0], B[j][1]);
                    MMA16816(acc[i][2 * j + 1], A[i], B[j][2], B[j][3]);
                }
        }
        __syncwarp();
        if (lane == 0) MBARRIER_ARRIVE(EMPTY + 8 * s);
        if (tid == 0 && it + 3 < 4) {
            WAIT_PARITY(EMPTY + 8 * s, ph);
            const int nk = it + 3;
            const uint32_t base = STG0 + s * WSTG_B;
            MBARRIER_EXPECT_TX(FULL + 8 * s, WSTG_B);
            bulk_g2s(base,         bhsrc + (size_t)nk * 16384, 16384, FULL + 8 * s);
            bulk_g2s(base + 16384, ahsrc + (size_t)nk * 16384, 16384, FULL + 8 * s);
        }
    }

    // epilogue: Weff = W + delta -> fp16, write into g_whi tile layout
    const int trow0 = warp_m * 64 + (lane >> 2);        // o within 128
    const int col0  = warp_n * 32 + (lane & 3) * 2;     // i within 128

#pragma unroll
    for (int t = 0; t < 4; t++) {
        const int col = col0 + t * 8;
        const int ig  = bI * 128 + col;
        const size_t tile = ((size_t)bO * 64 + (ig >> 6)) * 16384;
        const uint32_t cu2 = (uint32_t)(ig & 63) * 2;
#pragma unroll
        for (int i = 0; i < 4; i++) {
            const int r0 = trow0 + i * 16;
            const float2 w0 = *(const float2*)&W[(size_t)(bO * 128 + r0) * IN_DIM + ig];
            const float2 w1 = *(const float2*)&W[(size_t)(bO * 128 + r0 + 8) * IN_DIM + ig];
            const uint32_t v0 = h2u(__float2half_rn(w0.x + acc[i][t][0]),
                                    __float2half_rn(w0.y + acc[i][t][1]));
            const uint32_t v1 = h2u(__float2half_rn(w1.x + acc[i][t][2]),
                                    __float2half_rn(w1.y + acc[i][t][3]));
            *(uint32_t*)((char*)g_whi + tile + sw128((uint32_t)r0 * 128 + cu2))       = v0;
            *(uint32_t*)((char*)g_whi + tile + sw128((uint32_t)(r0 + 8) * 128 + cu2)) = v1;
        }
    }
}

// ---------------------------------------------------------------------------
// Kernel 4: PERSISTENT mma.sync mainloop.
//   grid = 148 CTAs (1/SM). Each walks tiles bid, bid+148, ... of the
//   16(bN) x 64(bM) tile space with one continuous 4-stage pipeline.
//   CTA tile: M=128 (t) x N=256 (o), K-chunk 64, 8 warps, warp tile 64x64.
// ---------------------------------------------------------------------------
#define STAGES    4
#define STAGE_B   49152
#define SMEM_MAIN (1024 + STAGES * STAGE_B)

__global__ __launch_bounds__(256, 1) void vera_mma_main(
    const float* __restrict__ bias, float* __restrict__ y)
{
    extern __shared__ char smem[];
    const uint32_t sb = smem_u32(smem);
    const int tid  = threadIdx.x;
    const int lane = tid & 31;
    const int wid  = tid >> 5;
    const int warp_m = wid >> 2;
    const int warp_n = wid & 3;
    const int bid = blockIdx.x;

    const uint32_t FULL  = sb;
    const uint32_t EMPTY = sb + 32;
    const uint32_t STG0  = sb + 1024;

    if (tid == 0) {
        for (int s = 0; s < STAGES; s++) {
            MBARRIER_INIT(FULL  + 8 * s, 1);
            MBARRIER_INIT(EMPTY + 8 * s, 8);
        }
    }
    __syncthreads();

    const int ntile = (NTILES - 1 - bid) / NSM + 1;   // 6 or 7
    const int NITER = ntile * 64;

    // prologue fills (first tile, k = 0..3)
    if (tid == 0) {
        const int tile0 = bid;
        const char* xs = (const char*)g_xhi + (size_t)(tile0 >> 4) * 64 * 16384;
        const char* ws = (const char*)g_whi + (size_t)((tile0 & 15) * 2) * 64 * 16384;
#pragma unroll
        for (int s = 0; s < STAGES; s++) {
            const uint32_t base = STG0 + s * STAGE_B;
            MBARRIER_EXPECT_TX(FULL + 8 * s, STAGE_B);
            bulk_g2s(base,         xs + (size_t)s * 16384, 16384, FULL + 8 * s);
            bulk_g2s(base + 16384, ws + (size_t)s * 16384, 16384, FULL + 8 * s);
            bulk_g2s(base + 32768, ws + (size_t)(64 + s) * 16384, 16384, FULL + 8 * s);
        }
    }

    const int a_row      = warp_m * 64 + (lane & 15);
    const uint32_t a_rb  = (uint32_t)a_row * 128;
    const uint32_t amsk  = (uint32_t)(lane & 7) << 4;
    const uint32_t acol0 = (uint32_t)(lane >> 4) * 16;

    const int b_rowl     = (warp_n & 1) * 64 + (lane & 7) + ((lane >> 4) & 1) * 8;
    const uint32_t b_rb  = (uint32_t)((warp_n >> 1) * 16384 + b_rowl * 128);
    const uint32_t bmsk  = (uint32_t)(lane & 7) << 4;
    const uint32_t bcol0 = (uint32_t)((lane >> 3) & 1) * 16;

    float acc[4][8][4];
#pragma unroll
    for (int i = 0; i < 4; i++)
#pragma unroll
        for (int t = 0; t < 8; t++)
#pragma unroll
            for (int q = 0; q < 4; q++) acc[i][t][q] = 0.0f;

#pragma unroll 1
    for (int p = 0; p < NITER; ++p) {
        const int s  = p & 3;
        const int ph = (p >> 2) & 1;
        WAIT_PARITY(FULL + 8 * s, ph);
        const uint32_t XA = STG0 + s * STAGE_B;
        const uint32_t WB = XA + 16384;

#pragma unroll
        for (int ks = 0; ks < 4; ks++) {
            const uint32_t acsw = (acol0 + ks * 32) ^ amsk;
            const uint32_t bcsw = (bcol0 + ks * 32) ^ bmsk;
            uint32_t A[4][4], B[4][4];
#pragma unroll
            for (int i = 0; i < 4; i++)
                LDSM_X4(A[i], XA + a_rb + i * 2048 + acsw);
#pragma unroll
            for (int j = 0; j < 4; j++)
                LDSM_X4(B[j], WB + b_rb + j * 2048 + bcsw);
#pragma unroll
            for (int i = 0; i < 4; i++)
#pragma unroll
                for (int j = 0; j < 4; j++) {
                    MMA16816(acc[i][2 * j],     A[i], B[j][0], B[j][1]);
                    MMA16816(acc[i][2 * j + 1], A[i], B[j][2], B[j][3]);
                }
        }

        __syncwarp();
        if (lane == 0) MBARRIER_ARRIVE(EMPTY + 8 * s);

        // producer: refill this stage with iteration p+STAGES (crosses tiles)
        if (tid == 0 && p + STAGES < NITER) {
            WAIT_PARITY(EMPTY + 8 * s, ph);
            const int q    = p + STAGES;
            const int tile = bid + (q >> 6) * NSM;
            const int k    = q & 63;
            const char* xs = (const char*)g_xhi + (size_t)((tile >> 4) * 64 + k) * 16384;
            const char* ws = (const char*)g_whi + (size_t)((tile & 15) * 2 * 64 + k) * 16384;
            const uint32_t base = STG0 + s * STAGE_B;
            MBARRIER_EXPECT_TX(FULL + 8 * s, STAGE_B);
            bulk_g2s(base,         xs, 16384, FULL + 8 * s);
            bulk_g2s(base + 16384, ws, 16384, FULL + 8 * s);
            bulk_g2s(base + 32768, ws + (size_t)64 * 16384, 16384, FULL + 8 * s);
        }

        // tile epilogue
        if ((p & 63) == 63) {
            const int tile = bid + (p >> 6) * NSM;
            const int bM = tile >> 4;
            const int bN = tile & 15;
            const int trow0 = bM * 128 + warp_m * 64 + (lane >> 2);
            const int col0g = bN * 256 + warp_n * 64 + (lane & 3) * 2;
#pragma unroll
            for (int t = 0; t < 8; t++) {
                const int col = col0g + t * 8;
                const float2 bv = *(const float2*)&bias[col];
#pragma unroll
                for (int i = 0; i < 4; i++) {
                    const int r0 = trow0 + i * 16;
                    float2 o0 = make_float2(acc[i][t][0] + bv.x, acc[i][t][1] + bv.y);
                    float2 o1 = make_float2(acc[i][t][2] + bv.x, acc[i][t][3] + bv.y);
                    *(float2*)&y[(size_t)r0 * OUT_DIM + col]       = o0;
                    *(float2*)&y[(size_t)(r0 + 8) * OUT_DIM + col] = o1;
                }
            }
#pragma unroll
            for (int i = 0; i < 4; i++)
#pragma unroll
                for (int t = 0; t < 8; t++)
#pragma unroll
                    for (int q = 0; q < 4; q++) acc[i][t][q] = 0.0f;
        }
    }
}

// ---------------------------------------------------------------------------
// Launch. Inputs: x, base_weight, base_bias, vera_random_A, vera_random_B,
//                 vera_d, vera_b
// ---------------------------------------------------------------------------
extern "C" void kernel_launch(void* const* d_in, const int* in_sizes, int n_in,
                              void* d_out, int out_size)
{
    const float* x    = (const float*)d_in[0];
    const float* W    = (const float*)d_in[1];
    const float* bias = (const float*)d_in[2];
    const float* vA   = (const float*)d_in[3];
    const float* vB   = (const float*)d_in[4];
    const float* vd   = (const float*)d_in[5];
    const float* vb   = (const float*)d_in[6];
    float* y = (float*)d_out;

    cudaFuncSetAttribute(vera_weff_mma,
                         cudaFuncAttributeMaxDynamicSharedMemorySize, WSMEM);
    cudaFuncSetAttribute(vera_mma_main,
                         cudaFuncAttributeMaxDynamicSharedMemorySize, SMEM_MAIN);

    vera_conv<<<1536, 256>>>(vB, vb, vA, vd);
    vera_x_split<<<(T_DIM * IN_DIM / 8) / 256, 256>>>(x);

    dim3 gweff(IN_DIM / 128, OUT_DIM / 128);   // 32 x 32
    vera_weff_mma<<<gweff, 256, WSMEM>>>(W);

    vera_mma_main<<<NSM, 256, SMEM_MAIN>>>(bias, y);
}